// round 6
// baseline (speedup 1.0000x reference)
#include <cuda_runtime.h>
#include <cuda_bf16.h>
#include <cstdint>

#define BMAX    64
#define MA      96
#define NDIM    256
#define EPSF    1e-8f
#define SLAB_F4 2304                 // 96*96/4 float4 per slab
#define NSLABS  (BMAX * MA)          // 6144
#define GRID2   296                  // 2 blocks per SM * 148 SMs

// Scatter buffer for padded node scores [B, MAX_A]. Zero-init at module load;
// invalid positions never written (and paths is 0 there anyway).
__device__ float g_sp[BMAX * MA];

__device__ __forceinline__ void cp16(float4* dst_smem, const float4* src_gmem) {
    uint32_t d = (uint32_t)__cvta_generic_to_shared(dst_smem);
    asm volatile("cp.async.cg.shared.global [%0], [%1], 16;\n"
                 :: "r"(d), "l"(src_gmem) : "memory");
}
__device__ __forceinline__ void cp_commit() {
    asm volatile("cp.async.commit_group;\n" ::: "memory");
}
__device__ __forceinline__ void cp_wait2() {
    asm volatile("cp.async.wait_group 2;\n" ::: "memory");
}

// ---------------------------------------------------------------------------
// Kernel 1: scores = x @ W[0] + b[0], scattered into g_sp via pad_idx.
// ---------------------------------------------------------------------------
__global__ void score_scatter_kernel(const float* __restrict__ x,
                                     const float* __restrict__ W,
                                     const float* __restrict__ bscal,
                                     const int*   __restrict__ pad_idx,
                                     int total) {
    int gwarp = (blockIdx.x * blockDim.x + threadIdx.x) >> 5;
    int lane  = threadIdx.x & 31;
    if (gwarp >= total) return;

    const float4* xr = reinterpret_cast<const float4*>(x + (size_t)gwarp * NDIM);
    const float4* wr = reinterpret_cast<const float4*>(W);

    float s = 0.0f;
    #pragma unroll
    for (int i = 0; i < 2; i++) {
        float4 a  = xr[lane + i * 32];
        float4 ww = wr[lane + i * 32];
        s += a.x * ww.x + a.y * ww.y + a.z * ww.z + a.w * ww.w;
    }
    #pragma unroll
    for (int o = 16; o > 0; o >>= 1)
        s += __shfl_xor_sync(0xFFFFFFFFu, s, o);

    if (lane == 0)
        g_sp[pad_idx[gwarp]] = s + bscal[0];
}

// ---------------------------------------------------------------------------
// Kernel 2: persistent TRIPLE-buffered cp.async pipeline over slabs.
// Two full slabs (72 KB) in flight per block at all times (wait_group 2),
// smoothing DRAM request issue across the compute/barrier phases.
// Compute: 192 threads = 2 per row (12 f4 each, XOR-swizzled conflict-free
// LDS.128), one shfl-pair to combine.
// ---------------------------------------------------------------------------
extern __shared__ float4 s_dyn[];   // [3][SLAB_F4] slabs, then [24] sp

__global__ __launch_bounds__(256) void path_avg_kernel(
        const float4* __restrict__ paths4,
        float*        __restrict__ out) {
    float4* sp_s = s_dyn + 3 * SLAB_F4;   // 24 float4 = 96 floats
    const float4* g_sp4 = reinterpret_cast<const float4*>(g_sp);

    int t  = threadIdx.x;
    int nb = gridDim.x;
    int s0 = blockIdx.x;

    // Stage slab -> buffer with XOR swizzle, 9 cp.async per thread.
    auto stage = [&](int slab, float4* dst) {
        if (slab < NSLABS) {
            const float4* src = paths4 + (size_t)slab * SLAB_F4;
            #pragma unroll
            for (int i = 0; i < 9; i++) {
                int f = t + i * 256;
                int r = f / 24;
                int c = f - r * 24;
                cp16(dst + r * 24 + (c ^ (r & 7)), src + f);
            }
        }
        cp_commit();   // unconditional: keeps group numbering exact
    };

    // Prologue: slabs k=0 and k=1 in flight.
    stage(s0,      s_dyn);
    stage(s0 + nb, s_dyn + SLAB_F4);

    int k = 0;
    for (int s = s0; s < NSLABS; s += nb, k++) {
        // sp for this slab's graph (prev compute done at trailing barrier)
        if (t < 24) sp_s[t] = g_sp4[(s / MA) * 24 + t];

        // Stage slab k+2 into the buffer freed at iteration k-1.
        int bnext = (k + 2) % 3;
        stage(s + 2 * nb, s_dyn + bnext * SLAB_F4);

        cp_wait2();              // commit k complete -> cur resident
        __syncthreads();

        const float4* cur = s_dyn + (k % 3) * SLAB_F4;
        if (t < 192) {
            int r  = t >> 1;
            int h  = t & 1;
            int sw = r & 7;
            const float4* row = cur + r * 24;
            float num = 0.0f, den = 0.0f;
            #pragma unroll
            for (int j = 0; j < 12; j++) {
                int c = h * 12 + j;
                float4 p = row[c ^ sw];
                float4 sv = sp_s[c];
                num += p.x * sv.x + p.y * sv.y + p.z * sv.z + p.w * sv.w;
                den += (p.x + p.y) + (p.z + p.w);
            }
            num += __shfl_xor_sync(0xFFFFFFFFu, num, 1);
            den += __shfl_xor_sync(0xFFFFFFFFu, den, 1);
            if (h == 0)
                out[(size_t)s * MA + r] = num / (den + EPSF);
        }
        __syncthreads();         // cur + sp_s free for reuse
    }
}

// ---------------------------------------------------------------------------
// Launch. Inputs (metadata order): x, W, b, paths, pad_idx.
// ---------------------------------------------------------------------------
extern "C" void kernel_launch(void* const* d_in, const int* in_sizes, int n_in,
                              void* d_out, int out_size) {
    const float*  x       = (const float*)d_in[0];
    const float*  W       = (const float*)d_in[1];
    const float*  bscal   = (const float*)d_in[2];
    const float4* paths4  = (const float4*)d_in[3];
    const int*    pad_idx = (const int*)d_in[4];
    float*        out     = (float*)d_out;

    int total = in_sizes[4];

    // 1: scores + scatter
    int blocks1 = (total * 32 + 255) / 256;
    score_scatter_kernel<<<blocks1, 256>>>(x, W, bscal, pad_idx, total);

    // 2: persistent triple-buffered pass over paths
    size_t smem = (3 * SLAB_F4 + 24) * sizeof(float4);   // 110976 B
    cudaFuncSetAttribute(path_avg_kernel,
                         cudaFuncAttributeMaxDynamicSharedMemorySize,
                         (int)smem);
    path_avg_kernel<<<GRID2, 256, smem>>>(paths4, out);
}

// round 7
// speedup vs baseline: 1.0067x; 1.0067x over previous
#include <cuda_runtime.h>
#include <cuda_bf16.h>
#include <cstdint>

#define BMAX    64
#define MA      96
#define NDIM    256
#define EPSF    1e-8f
#define SLAB_F4 2304                 // 96*96/4 float4 per slab
#define NSLABS  (BMAX * MA)          // 6144
#define GRID3   444                  // 3 blocks per SM * 148 SMs

// Scatter buffer for padded node scores [B, MAX_A]. Zero-init at module load;
// invalid positions never written (and paths is 0 there anyway).
__device__ float g_sp[BMAX * MA];

__device__ __forceinline__ void cp16(float4* dst_smem, const float4* src_gmem) {
    uint32_t d = (uint32_t)__cvta_generic_to_shared(dst_smem);
    asm volatile("cp.async.cg.shared.global [%0], [%1], 16;\n"
                 :: "r"(d), "l"(src_gmem) : "memory");
}
__device__ __forceinline__ void cp_commit() {
    asm volatile("cp.async.commit_group;\n" ::: "memory");
}
__device__ __forceinline__ void cp_wait1() {
    asm volatile("cp.async.wait_group 1;\n" ::: "memory");
}

// ---------------------------------------------------------------------------
// Kernel 1: scores = x @ W[0] + b[0], scattered into g_sp via pad_idx.
// ---------------------------------------------------------------------------
__global__ void score_scatter_kernel(const float* __restrict__ x,
                                     const float* __restrict__ W,
                                     const float* __restrict__ bscal,
                                     const int*   __restrict__ pad_idx,
                                     int total) {
    int gwarp = (blockIdx.x * blockDim.x + threadIdx.x) >> 5;
    int lane  = threadIdx.x & 31;
    if (gwarp >= total) return;

    const float4* xr = reinterpret_cast<const float4*>(x + (size_t)gwarp * NDIM);
    const float4* wr = reinterpret_cast<const float4*>(W);

    float s = 0.0f;
    #pragma unroll
    for (int i = 0; i < 2; i++) {
        float4 a  = xr[lane + i * 32];
        float4 ww = wr[lane + i * 32];
        s += a.x * ww.x + a.y * ww.y + a.z * ww.z + a.w * ww.w;
    }
    #pragma unroll
    for (int o = 16; o > 0; o >>= 1)
        s += __shfl_xor_sync(0xFFFFFFFFu, s, o);

    if (lane == 0)
        g_sp[pad_idx[gwarp]] = s + bscal[0];
}

// ---------------------------------------------------------------------------
// Kernel 2: persistent double-buffered cp.async pipeline, 3 blocks/SM.
// Each block grid-strides over slabs; prefetches slab k+1 into the other
// buffer while computing slab k. Compute: 192 threads = 2 per row (12 f4
// each, XOR-swizzled conflict-free LDS.128), one shfl-pair to combine.
// ---------------------------------------------------------------------------
extern __shared__ float4 s_dyn[];   // [2][SLAB_F4] slabs, then [24] sp

__global__ __launch_bounds__(256) void path_avg_kernel(
        const float4* __restrict__ paths4,
        float*        __restrict__ out) {
    float4* buf0 = s_dyn;
    float4* buf1 = s_dyn + SLAB_F4;
    float4* sp_s = s_dyn + 2 * SLAB_F4;   // 24 float4 = 96 floats
    const float4* g_sp4 = reinterpret_cast<const float4*>(g_sp);

    int t  = threadIdx.x;
    int nb = gridDim.x;
    int s0 = blockIdx.x;

    // Stage slab -> buffer with XOR swizzle, 9 cp.async per thread.
    auto stage = [&](int slab, float4* dst) {
        if (slab < NSLABS) {
            const float4* src = paths4 + (size_t)slab * SLAB_F4;
            #pragma unroll
            for (int i = 0; i < 9; i++) {
                int f = t + i * 256;
                int r = f / 24;
                int c = f - r * 24;
                cp16(dst + r * 24 + (c ^ (r & 7)), src + f);
            }
        }
        cp_commit();   // unconditional: keeps group numbering exact
    };

    stage(s0, buf0);

    int k = 0;
    for (int s = s0; s < NSLABS; s += nb, k++) {
        // sp for this slab's graph (prev compute done at trailing barrier)
        if (t < 24) sp_s[t] = g_sp4[(s / MA) * 24 + t];

        float4* cur = (k & 1) ? buf1 : buf0;
        float4* nxt = (k & 1) ? buf0 : buf1;
        stage(s + nb, nxt);

        cp_wait1();              // slab s resident (s+nb may be in flight)
        __syncthreads();

        if (t < 192) {
            int r  = t >> 1;
            int h  = t & 1;
            int sw = r & 7;
            const float4* row = cur + r * 24;
            float num = 0.0f, den = 0.0f;
            #pragma unroll
            for (int j = 0; j < 12; j++) {
                int c = h * 12 + j;
                float4 p = row[c ^ sw];
                float4 sv = sp_s[c];
                num += p.x * sv.x + p.y * sv.y + p.z * sv.z + p.w * sv.w;
                den += (p.x + p.y) + (p.z + p.w);
            }
            num += __shfl_xor_sync(0xFFFFFFFFu, num, 1);
            den += __shfl_xor_sync(0xFFFFFFFFu, den, 1);
            if (h == 0)
                out[(size_t)s * MA + r] = num / (den + EPSF);
        }
        __syncthreads();         // cur + sp_s free for reuse
    }
}

// ---------------------------------------------------------------------------
// Launch. Inputs (metadata order): x, W, b, paths, pad_idx.
// ---------------------------------------------------------------------------
extern "C" void kernel_launch(void* const* d_in, const int* in_sizes, int n_in,
                              void* d_out, int out_size) {
    const float*  x       = (const float*)d_in[0];
    const float*  W       = (const float*)d_in[1];
    const float*  bscal   = (const float*)d_in[2];
    const float4* paths4  = (const float4*)d_in[3];
    const int*    pad_idx = (const int*)d_in[4];
    float*        out     = (float*)d_out;

    int total = in_sizes[4];

    // 1: scores + scatter
    int blocks1 = (total * 32 + 255) / 256;
    score_scatter_kernel<<<blocks1, 256>>>(x, W, bscal, pad_idx, total);

    // 2: persistent double-buffered pass over paths, 3 blocks/SM
    size_t smem = (2 * SLAB_F4 + 24) * sizeof(float4);   // 74112 B
    cudaFuncSetAttribute(path_avg_kernel,
                         cudaFuncAttributeMaxDynamicSharedMemorySize,
                         (int)smem);
    path_avg_kernel<<<GRID3, 256, smem>>>(paths4, out);
}